// round 7
// baseline (speedup 1.0000x reference)
#include <cuda_runtime.h>
#include <math.h>

#define NB 16
#define NA 5
#define NH 96
#define NW 96
#define NHW 9216
#define TT 50
#define ROWS 4
#define TPB (ROWS * NW)                 // 384 threads
#define ROWGRP (NH / ROWS)              // 24
#define DENSE_BX (NA * ROWGRP)          // 120 dense blocks per batch
#define N_PART (DENSE_BX * NB)          // 1920

__constant__ float c_aw[NA] = {1.3221f, 3.19275f, 5.05587f, 9.47112f, 11.2364f};
__constant__ float c_ah[NA] = {1.73145f, 4.00944f, 8.09892f, 4.84053f, 10.0071f};

__device__ float g_part[N_PART];
__device__ float g_sparsef[NB];

__device__ __forceinline__ float sigmoidf_(float x) { return 1.f / (1.f + __expf(-x)); }

// ---------------------------------------------------------------------------
// ONE fused kernel, grid = (121, 16), block = 384. Float-only (low regs).
//   blockIdx.x < 120 : dense no-object term, 4 rows x 1 anchor, band-pruned.
//   blockIdx.x == 120: sparse per-target loss (parses targets itself).
// Each block parses its batch's 300-float target slab via coalesced float4.
// No atomics, no fences, no doubles.
// ---------------------------------------------------------------------------
__global__ void __launch_bounds__(TPB)
fused_kernel(const float* __restrict__ out, const float* __restrict__ tgt)
{
    __shared__ float  s_tgt[TT * 6];       // raw target slab for this batch
    __shared__ float4 sA[TT + 4];          // gt extents: xlo, xhi, ylo, yhi
    __shared__ float  sbz[TT + 4];         // 0.6 * gt area
    __shared__ int    sidx[TT];            // sparse path: scatter cell per target
    __shared__ int    smaskZ[2];           // ballot: xr == 0
    __shared__ int    smaskK[2];           // ballot: band-prune keep candidate
    __shared__ float  wsum[TPB / 32];

    const int b = blockIdx.y;
    const int bx = blockIdx.x;
    const int tid = threadIdx.x;

    if (bx < DENSE_BX) {
        // =================== DENSE PATH ===================
        const int a = bx / ROWGRP;
        const int j0 = (bx - a * ROWGRP) * ROWS;
        const int jr = tid / NW;
        const int i = tid - jr * NW;
        const int j = j0 + jr;

        // issue output loads first (independent of target slab)
        const float* op = out + ((b * NA + a) * 8) * NHW + j * NW + i;
        const float o0 = op[0];
        const float o1 = op[NHW];
        const float o2 = op[2 * NHW];
        const float o3 = op[3 * NHW];
        const float o4 = op[4 * NHW];

        // coalesced target slab load: 300 floats = 75 float4
        if (tid < 75)
            reinterpret_cast<float4*>(s_tgt)[tid] =
                reinterpret_cast<const float4*>(tgt + b * (TT * 6))[tid];
        __syncthreads();

        // parse + band prune + both ballots in ONE round
        float xr = 1.f, bz = 0.f;
        float4 ext = make_float4(0.f, 0.f, 0.f, 0.f);
        bool kc = false;
        if (tid < 64) {
            if (tid < TT) {
                const float* tp = s_tgt + tid * 6;
                xr = tp[1];
                const float gx = xr * NW;
                const float gy = tp[2] * NH;
                const float gw = tp[3] * NW;
                const float gh = tp[4] * NH;
                ext = make_float4(gx - 0.5f * gw, gx + 0.5f * gw,
                                  gy - 0.5f * gh, gy + 0.5f * gh);
                bz = 0.6f * (gw * gh);
                const float band = gh * (1.f / 3.f) + 0.25f;
                kc = ((float)j0 < ext.w + band) && ((float)(j0 + ROWS) > ext.z - band);
            }
            const unsigned zm = __ballot_sync(0xffffffffu, xr == 0.f);
            const unsigned km = __ballot_sync(0xffffffffu, kc);
            if ((tid & 31) == 0) { smaskZ[tid >> 5] = (int)zm; smaskK[tid >> 5] = (int)km; }
        }
        __syncthreads();

        const unsigned z0 = (unsigned)smaskZ[0];
        const unsigned z1 = (unsigned)smaskZ[1];
        const int nv = z0 ? (__ffs(z0) - 1) : (z1 ? 32 + __ffs(z1) - 1 : TT);
        const unsigned v0 = (nv >= 32) ? 0xffffffffu : ((1u << nv) - 1u);
        const unsigned v1 = (nv <= 32) ? 0u : ((1u << (nv - 32)) - 1u);
        const unsigned m0 = (unsigned)smaskK[0] & v0;
        const unsigned m1 = (unsigned)smaskK[1] & v1;
        const int cnt = __popc(m0) + __popc(m1);

        const bool keep = (tid < 32) ? (((m0 >> tid) & 1u) != 0u)
                                     : ((tid < 64) ? (((m1 >> (tid - 32)) & 1u) != 0u) : false);
        if (keep) {
            const int pos = (tid < 32) ? __popc(m0 & ((1u << tid) - 1u))
                                       : __popc(m0) + __popc(m1 & ((1u << (tid - 32)) - 1u));
            sA[pos] = ext;
            sbz[pos] = bz;
        }
        if (tid < 4) {   // never-firing pad so the chunk-4 loop needs no tail
            sA[cnt + tid] = make_float4(1e30f, -1e30f, 1e30f, -1e30f);
            sbz[cnt + tid] = 0.f;
        }
        __syncthreads();

        const float px = sigmoidf_(o0) + (float)i;
        const float py = sigmoidf_(o1) + (float)j;
        const float pw = __expf(o2) * c_aw[a];
        const float ph = __expf(o3) * c_ah[a];

        const float xlo = px - 0.5f * pw, xhi = px + 0.5f * pw;
        const float ylo = py - 0.5f * ph, yhi = py + 0.5f * ph;
        const float c1 = 0.6f * (pw * ph);

        bool over = false;
        for (int k = 0; k < cnt; k += 4) {
            bool f = false;
#pragma unroll
            for (int u = 0; u < 4; u++) {
                const float4 a4 = sA[k + u];
                const float iw = fminf(xhi, a4.y) - fmaxf(xlo, a4.x);
                const float ih = fminf(yhi, a4.w) - fmaxf(ylo, a4.z);
                f |= (fminf(iw, ih) > 0.f) && (fmaf(1.6f, iw * ih, -sbz[k + u]) > c1);
            }
            if (f) { over = true; break; }
        }

        const float conf = sigmoidf_(o4);
        float term = over ? 0.f : 0.5f * conf * conf;

#pragma unroll
        for (int off = 16; off > 0; off >>= 1)
            term += __shfl_down_sync(0xffffffffu, term, off);
        if ((tid & 31) == 0) wsum[tid >> 5] = term;
        __syncthreads();
        if (tid == 0) {
            float s = 0.f;
#pragma unroll
            for (int k = 0; k < TPB / 32; k++) s += wsum[k];
            g_part[b * DENSE_BX + bx] = s;    // plain store, no atomic
        }
        return;
    }

    // =================== SPARSE PATH (one block per batch) ===================
    if (tid < 75)
        reinterpret_cast<float4*>(s_tgt)[tid] =
            reinterpret_cast<const float4*>(tgt + b * (TT * 6))[tid];
    __syncthreads();

    float xr = 1.f, tcls = 0.f, gx = 0.f, gy = 0.f, gw = 0.f, gh = 0.f, lr = 0.f;
    int bn = 0, gi = 0, gj = 0, idx = 0;
    if (tid < 64) {
        if (tid < TT) {
            const float* tp = s_tgt + tid * 6;
            tcls = tp[0];
            xr = tp[1];
            gx = xr * NW;
            gy = tp[2] * NH;
            gw = tp[3] * NW;
            gh = tp[4] * NH;
            lr = tp[5];

            const float area = gw * gh;
            float best = -1.f;
#pragma unroll
            for (int k = 0; k < NA; k++) {
                const float inter = fminf(gw, c_aw[k]) * fminf(gh, c_ah[k]);
                const float iou = inter / (area + c_aw[k] * c_ah[k] - inter);
                if (iou > best) { best = iou; bn = k; }
            }
            gi = (int)gx;
            gj = (int)gy;
            idx = bn * NHW + gj * NW + gi;
            sidx[tid] = idx;
            sA[tid] = make_float4(gx - 0.5f * gw, gx + 0.5f * gw,
                                  gy - 0.5f * gh, gy + 0.5f * gh);
            sbz[tid] = 0.6f * area;
        }
        const unsigned zm = __ballot_sync(0xffffffffu, xr == 0.f);
        if ((tid & 31) == 0) smaskZ[tid >> 5] = (int)zm;
    }
    __syncthreads();
    const unsigned z0 = (unsigned)smaskZ[0];
    const unsigned z1 = (unsigned)smaskZ[1];
    const int nv = z0 ? (__ffs(z0) - 1) : (z1 ? 32 + __ffs(z1) - 1 : TT);

    // last-valid-write-wins ownership
    bool owner = tid < nv;
    if (owner)
        for (int t2 = tid + 1; t2 < nv; t2++)
            if (sidx[t2] == idx) { owner = false; break; }

    float c = 0.f;
    if (owner) {
        const int hw = idx - bn * NHW;
        const float* op = out + ((b * NA + bn) * 8) * NHW + hw;
        const float o0 = op[0];
        const float o1 = op[NHW];
        const float o2 = op[2 * NHW];
        const float o3 = op[3 * NHW];
        const float o4 = op[4 * NHW];
        const float o5 = op[5 * NHW];
        const float o6 = op[6 * NHW];
        const float o7 = op[7 * NHW];

        const float x = sigmoidf_(o0);
        const float y = sigmoidf_(o1);
        const float px = x + (float)gi;
        const float py = y + (float)gj;
        const float pw = __expf(o2) * c_aw[bn];
        const float ph = __expf(o3) * c_ah[bn];

        const float tx = gx - (float)gi;
        const float ty = gy - (float)gj;
        const float tw = __logf(gw / c_aw[bn]);
        const float th = __logf(gh / c_ah[bn]);

        const float xlo = px - 0.5f * pw, xhi = px + 0.5f * pw;
        const float ylo = py - 0.5f * ph, yhi = py + 0.5f * ph;

        // tconf = IoU(gt, pred_at)
        const float iw = fminf(gx + 0.5f * gw, xhi) - fmaxf(gx - 0.5f * gw, xlo);
        const float ih = fminf(gy + 0.5f * gh, yhi) - fmaxf(gy - 0.5f * gh, ylo);
        const float ca = (iw > 0.f && ih > 0.f) ? iw * ih : 0.f;
        const float tconf = ca / (gw * gh + pw * ph - ca);

        const float conf = sigmoidf_(o4);

        // full-list over predicate (identical expression to the dense path)
        const float c1 = 0.6f * (pw * ph);
        bool over = false;
        for (int k = 0; k < nv; k++) {
            const float4 a4 = sA[k];
            const float iw2 = fminf(xhi, a4.y) - fmaxf(xlo, a4.x);
            const float ih2 = fminf(yhi, a4.w) - fmaxf(ylo, a4.z);
            if ((fminf(iw2, ih2) > 0.f) &&
                (fmaf(1.6f, iw2 * ih2, -sbz[k]) > c1)) { over = true; break; }
        }

        const float dx = x - tx;   c += 0.5f * dx * dx;
        const float dy = y - ty;   c += 0.5f * dy * dy;
        const float dw = o2 - tw;  c += 0.5f * dw * dw;
        const float dh = o3 - th;  c += 0.5f * dh * dh;
        const float dc = conf - tconf;
        c += 2.5f * dc * dc;                     // 0.5 * OBJECT_SCALE
        if (!over) c -= 0.5f * conf * conf;      // cancel dense default term

        const float m = fmaxf(o5, o6);
        const float lse = m + __logf(__expf(o5 - m) + __expf(o6 - m));
        c += lse - (((int)tcls) == 0 ? o5 : o6);

        const float clr = sigmoidf_(o7);
        const float dl = clr - lr;
        c += 0.25f * dl * dl;
    }

#pragma unroll
    for (int off = 16; off > 0; off >>= 1)
        c += __shfl_down_sync(0xffffffffu, c, off);
    if ((tid & 31) == 0) wsum[tid >> 5] = c;
    __syncthreads();
    if (tid == 0) {
        float s = 0.f;
#pragma unroll
        for (int k = 0; k < TPB / 32; k++) s += wsum[k];
        g_sparsef[b] = s;
    }
}

// ---------------------------------------------------------------------------
// Kernel 2: sum 1920 partials + 16 sparse sums in double -> scalar.
// ---------------------------------------------------------------------------
__global__ void __launch_bounds__(256)
finalize_kernel(float* __restrict__ res)
{
    __shared__ double wsumd[8];
    const int tid = threadIdx.x;
    double s = 0.0;
    for (int k = tid; k < N_PART; k += 256) s += (double)g_part[k];
    if (tid < NB) s += (double)g_sparsef[tid];
#pragma unroll
    for (int off = 16; off > 0; off >>= 1)
        s += __shfl_down_sync(0xffffffffu, s, off);
    if ((tid & 31) == 0) wsumd[tid >> 5] = s;
    __syncthreads();
    if (tid == 0) {
        double t = 0.0;
#pragma unroll
        for (int k = 0; k < 8; k++) t += wsumd[k];
        res[0] = (float)(t / (double)NB);
    }
}

extern "C" void kernel_launch(void* const* d_in, const int* in_sizes, int n_in,
                              void* d_out, int out_size)
{
    const float* output = (const float*)d_in[0];
    const float* target = (const float*)d_in[1];
    float* res = (float*)d_out;

    fused_kernel<<<dim3(DENSE_BX + 1, NB), TPB>>>(output, target);
    finalize_kernel<<<1, 256>>>(res);
}

// round 8
// speedup vs baseline: 4.9156x; 4.9156x over previous
#include <cuda_runtime.h>
#include <math.h>

#define NB 16
#define NA 5
#define NH 96
#define NW 96
#define NHW 9216
#define TT 50
#define ROWS 4
#define TPB (ROWS * NW)                 // 384 threads
#define ROWGRP (NH / ROWS)              // 24
#define DENSE_BX (NA * ROWGRP)          // 120 dense blocks per batch
#define N_PART (DENSE_BX * NB)          // 1920

__constant__ float c_aw[NA] = {1.3221f, 3.19275f, 5.05587f, 9.47112f, 11.2364f};
__constant__ float c_ah[NA] = {1.73145f, 4.00944f, 8.09892f, 4.84053f, 10.0071f};

__device__ float4 g_tA[NB * TT];     // gt extents: xlo, xhi, ylo, yhi
__device__ float  g_bz[NB * TT];     // 0.6 * gt area
__device__ float  g_band[NB * TT];   // gh/3 + margin (prune half-band)
__device__ int    g_nv[NB];
__device__ float4 g_m0[NB * TT];     // gx, gy, gw, gh
__device__ float  g_lr[NB * TT];
__device__ int4   g_meta[NB * TT];   // idx(within batch), bn, owner, cls
__device__ double g_sparse[NB];
__device__ double g_part[N_PART];

__device__ __forceinline__ float sigmoidf_(float x) { return 1.f / (1.f + __expf(-x)); }

// ---------------------------------------------------------------------------
// Kernel 0: target parsing, anchor argmax, ownership. ONE block, 800 threads
// (the only parse shape measured fast). No ballots, no doubles.
// ---------------------------------------------------------------------------
__global__ void __launch_bounds__(NB * TT)
box_prep(const float* __restrict__ tgt)
{
    __shared__ int s_nv[NB];
    __shared__ int sidx[NB * TT];

    const int tid = threadIdx.x;      // 0..799
    const int b = tid / TT;
    const int t = tid - b * TT;

    if (tid < NB) s_nv[tid] = TT;
    __syncthreads();

    const float* tp = tgt + tid * 6;
    const float tcls = tp[0];
    const float xr = tp[1];
    const float gx = xr * NW;
    const float gy = tp[2] * NH;
    const float gw = tp[3] * NW;
    const float gh = tp[4] * NH;
    const float lr = tp[5];

    if (xr == 0.f) atomicMin(&s_nv[b], t);   // native int ATOMS

    // best anchor (first-index-wins, matching jnp.argmax)
    const float area = gw * gh;
    int bn = 0;
    float best = -1.f;
#pragma unroll
    for (int k = 0; k < NA; k++) {
        const float inter = fminf(gw, c_aw[k]) * fminf(gh, c_ah[k]);
        const float iou = inter / (area + c_aw[k] * c_ah[k] - inter);
        if (iou > best) { best = iou; bn = k; }
    }
    const int gi = (int)gx;
    const int gj = (int)gy;
    const int idx = bn * NHW + gj * NW + gi;
    sidx[tid] = idx;
    __syncthreads();

    const int nv = s_nv[b];
    const bool valid = t < nv;

    // last-valid-write-wins: owner iff no later valid target hits the same cell
    bool owner = valid;
    if (owner)
        for (int t2 = t + 1; t2 < nv; t2++)
            if (sidx[b * TT + t2] == idx) { owner = false; break; }

    g_tA[tid] = make_float4(gx - 0.5f * gw, gx + 0.5f * gw,
                            gy - 0.5f * gh, gy + 0.5f * gh);
    g_bz[tid] = 0.6f * area;
    g_band[tid] = gh * (1.f / 3.f) + 0.25f;
    g_m0[tid] = make_float4(gx, gy, gw, gh);
    g_lr[tid] = lr;
    g_meta[tid] = make_int4(idx, bn, owner ? 1 : 0, (int)tcls);
    if (t == 0) g_nv[b] = nv;
}

// ---------------------------------------------------------------------------
// Kernel 1: dense no-object term + sparse per-target loss.
// grid = (121, 16), block = 384.
//   blockIdx.x < 120 : dense (4 rows x 1 anchor), band-pruned, BRANCH-FREE loop
//   blockIdx.x == 120: sparse loss for batch blockIdx.y
// ---------------------------------------------------------------------------
__global__ void __launch_bounds__(TPB)
dense_kernel(const float* __restrict__ out)
{
    __shared__ float4 sA[TT + 4];
    __shared__ float  sbz[TT + 4];
    __shared__ int    smask[2];
    __shared__ int    s_nv;
    __shared__ float  wsum[TPB / 32];
    __shared__ double wsumd[TPB / 32];

    const int b = blockIdx.y;
    const int bx = blockIdx.x;
    const int tid = threadIdx.x;

    if (bx == DENSE_BX) {
        // =================== SPARSE PATH ===================
        if (tid == 0) s_nv = g_nv[b];
        if (tid < TT) {
            sA[tid] = g_tA[b * TT + tid];
            sbz[tid] = g_bz[b * TT + tid];
        }
        __syncthreads();
        const int nv = s_nv;

        double c = 0.0;
        if (tid < TT) {
            const int4 meta = g_meta[b * TT + tid];
            if (meta.z) {
                const int idx = meta.x, bn = meta.y, cls = meta.w;
                const int hw = idx - bn * NHW;
                const int gj = hw / NW;
                const int gi = hw - gj * NW;
                const float4 m0 = g_m0[b * TT + tid];
                const float gx = m0.x, gy = m0.y, gw = m0.z, gh = m0.w;
                const float lr = g_lr[b * TT + tid];

                const float* op = out + ((b * NA + bn) * 8) * NHW + hw;
                const float o0 = op[0];
                const float o1 = op[NHW];
                const float o2 = op[2 * NHW];
                const float o3 = op[3 * NHW];
                const float o4 = op[4 * NHW];
                const float o5 = op[5 * NHW];
                const float o6 = op[6 * NHW];
                const float o7 = op[7 * NHW];

                const float x = sigmoidf_(o0);
                const float y = sigmoidf_(o1);
                const float px = x + (float)gi;
                const float py = y + (float)gj;
                const float pw = __expf(o2) * c_aw[bn];
                const float ph = __expf(o3) * c_ah[bn];

                const float tx = gx - (float)gi;
                const float ty = gy - (float)gj;
                const float tw = __logf(gw / c_aw[bn]);
                const float th = __logf(gh / c_ah[bn]);

                const float xlo = px - 0.5f * pw, xhi = px + 0.5f * pw;
                const float ylo = py - 0.5f * ph, yhi = py + 0.5f * ph;

                // tconf = IoU(gt, pred_at)
                const float iw = fminf(gx + 0.5f * gw, xhi) - fmaxf(gx - 0.5f * gw, xlo);
                const float ih = fminf(gy + 0.5f * gh, yhi) - fmaxf(gy - 0.5f * gh, ylo);
                const float ca = (iw > 0.f && ih > 0.f) ? iw * ih : 0.f;
                const float tconf = ca / (gw * gh + pw * ph - ca);

                const float conf = sigmoidf_(o4);

                // over predicate — IDENTICAL branch-free expression to dense path
                const float c1 = 0.6f * (pw * ph);
                float bestm = -1.f;
                for (int k = 0; k < nv; k++) {
                    const float4 a4 = sA[k];
                    const float iw2 = fminf(xhi, a4.y) - fmaxf(xlo, a4.x);
                    const float ih2 = fminf(yhi, a4.w) - fmaxf(ylo, a4.z);
                    const float hit = fminf(fminf(iw2, ih2),
                                            fmaf(1.6f, iw2 * ih2, -sbz[k]) - c1);
                    bestm = fmaxf(bestm, hit);
                }
                const bool over = bestm > 0.f;

                const float dx = x - tx;   c += 0.5 * (double)(dx * dx);
                const float dy = y - ty;   c += 0.5 * (double)(dy * dy);
                const float dw = o2 - tw;  c += 0.5 * (double)(dw * dw);
                const float dh = o3 - th;  c += 0.5 * (double)(dh * dh);
                const float dc = conf - tconf;
                c += 2.5 * (double)(dc * dc);                 // 0.5 * OBJECT_SCALE
                if (!over) c -= (double)(0.5f * conf * conf); // cancel dense term

                const float m = fmaxf(o5, o6);
                const float lse = m + __logf(__expf(o5 - m) + __expf(o6 - m));
                c += (double)(lse - (cls == 0 ? o5 : o6));

                const float clr = sigmoidf_(o7);
                const float dl = clr - lr;
                c += 0.25 * (double)(dl * dl);
            }
        }
        // warp-shuffle double reduction, plain smem stores
#pragma unroll
        for (int off = 16; off > 0; off >>= 1)
            c += __shfl_down_sync(0xffffffffu, c, off);
        if ((tid & 31) == 0) wsumd[tid >> 5] = c;
        __syncthreads();
        if (tid == 0) {
            double s = 0.0;
#pragma unroll
            for (int k = 0; k < TPB / 32; k++) s += wsumd[k];
            g_sparse[b] = s;
        }
        return;
    }

    // =================== DENSE PATH ===================
    const int a = bx / ROWGRP;
    const int j0 = (bx - a * ROWGRP) * ROWS;
    const int jr = tid / NW;
    const int i = tid - jr * NW;
    const int j = j0 + jr;

    // issue output loads early
    const float* op = out + ((b * NA + a) * 8) * NHW + j * NW + i;
    const float o0 = op[0];
    const float o1 = op[NHW];
    const float o2 = op[2 * NHW];
    const float o3 = op[3 * NHW];
    const float o4 = op[4 * NHW];

    if (tid == 0) s_nv = g_nv[b];

    // coalesced load of precomputed boxes + band prune + ballot compaction
    float4 ext; float bz = 0.f;
    bool keep = false;
    if (tid < TT) {
        ext = g_tA[b * TT + tid];
        bz = g_bz[b * TT + tid];
        const float band = g_band[b * TT + tid];
        keep = ((float)j0 < ext.w + band) && ((float)(j0 + ROWS) > ext.z - band);
    }
    __syncthreads();                      // s_nv visible
    if (tid < 64) {
        keep = keep && (tid < s_nv);
        unsigned m = __ballot_sync(0xffffffffu, keep);
        if ((tid & 31) == 0) smask[tid >> 5] = (int)m;
    }
    __syncthreads();
    const unsigned m0 = (unsigned)smask[0];
    const unsigned m1 = (unsigned)smask[1];
    const int cnt = __popc(m0) + __popc(m1);
    if (keep) {
        const unsigned below = (tid < 32) ? (m0 & ((1u << tid) - 1u))
                                          : m1 & ((tid == 32) ? 0u : ((1u << (tid - 32)) - 1u));
        const int pos = ((tid < 32) ? 0 : __popc(m0)) + __popc(below);
        sA[pos] = ext;
        sbz[pos] = bz;
    }
    if (tid < 4) {   // never-firing pad so the chunk-4 loop needs no tail
        sA[cnt + tid] = make_float4(1e30f, -1e30f, 1e30f, -1e30f);
        sbz[cnt + tid] = 0.f;
    }
    __syncthreads();

    const float px = sigmoidf_(o0) + (float)i;
    const float py = sigmoidf_(o1) + (float)j;
    const float pw = __expf(o2) * c_aw[a];
    const float ph = __expf(o3) * c_ah[a];

    const float xlo = px - 0.5f * pw, xhi = px + 0.5f * pw;
    const float ylo = py - 0.5f * ph, yhi = py + 0.5f * ph;
    const float c1 = 0.6f * (pw * ph);

    // BRANCH-FREE inner loop: no early exit, pure min/max accumulation.
    float bestm = -1.f;
    for (int k = 0; k < cnt; k += 4) {
#pragma unroll
        for (int u = 0; u < 4; u++) {
            const float4 a4 = sA[k + u];
            const float iw = fminf(xhi, a4.y) - fmaxf(xlo, a4.x);
            const float ih = fminf(yhi, a4.w) - fmaxf(ylo, a4.z);
            const float hit = fminf(fminf(iw, ih),
                                    fmaf(1.6f, iw * ih, -sbz[k + u]) - c1);
            bestm = fmaxf(bestm, hit);
        }
    }
    const bool over = bestm > 0.f;

    const float conf = sigmoidf_(o4);
    float term = over ? 0.f : 0.5f * conf * conf;

#pragma unroll
    for (int off = 16; off > 0; off >>= 1)
        term += __shfl_down_sync(0xffffffffu, term, off);
    if ((tid & 31) == 0) wsum[tid >> 5] = term;
    __syncthreads();
    if (tid == 0) {
        float s = 0.f;
#pragma unroll
        for (int k = 0; k < TPB / 32; k++) s += wsum[k];
        g_part[b * DENSE_BX + bx] = (double)s;   // plain store, no atomic
    }
}

// ---------------------------------------------------------------------------
// Kernel 2: sum 1920 partials + 16 sparse sums -> scalar.
// ---------------------------------------------------------------------------
__global__ void __launch_bounds__(256)
finalize_kernel(float* __restrict__ res)
{
    __shared__ double wsumd[8];
    const int tid = threadIdx.x;
    double s = 0.0;
    for (int k = tid; k < N_PART; k += 256) s += g_part[k];
    if (tid < NB) s += g_sparse[tid];
#pragma unroll
    for (int off = 16; off > 0; off >>= 1)
        s += __shfl_down_sync(0xffffffffu, s, off);
    if ((tid & 31) == 0) wsumd[tid >> 5] = s;
    __syncthreads();
    if (tid == 0) {
        double t = 0.0;
#pragma unroll
        for (int k = 0; k < 8; k++) t += wsumd[k];
        res[0] = (float)(t / (double)NB);
    }
}

extern "C" void kernel_launch(void* const* d_in, const int* in_sizes, int n_in,
                              void* d_out, int out_size)
{
    const float* output = (const float*)d_in[0];
    const float* target = (const float*)d_in[1];
    float* res = (float*)d_out;

    box_prep<<<1, NB * TT>>>(target);
    dense_kernel<<<dim3(DENSE_BX + 1, NB), TPB>>>(output);
    finalize_kernel<<<1, 256>>>(res);
}